// round 2
// baseline (speedup 1.0000x reference)
#include <cuda_runtime.h>
#include <math.h>

// Problem constants (fixed by the reference):
//   x: (B=4, S=128, H=128, W=128) fp32
//   ada_mask: (B, S, K=21) fp32
//   out[b,s,h,w] = sum_k softmax(ada_mask[b,s,:])[k] * xpad[b, s+k-10, h, w]
#define B_DIM   4
#define S_DIM   128
#define HW_DIM  16384            // H*W
#define K_DIM   21
#define PAD     10
#define TILE_S  32               // outputs in s per thread
#define THREADS 256
#define WROW    24               // weight row padded to 24 floats (zeros at 21..23)
#define WIN     (TILE_S + WROW - 1)  // 55 input planes per tile (extra 3 hit zero weights)

__global__ __launch_bounds__(THREADS, 2)
void AdaptiveMixing_28784870818046_kernel(const float* __restrict__ x,
                                          const float* __restrict__ ada_mask,
                                          float* __restrict__ out)
{
    __shared__ __align__(16) float ws[TILE_S * WROW];

    const int b  = blockIdx.z;
    const int s0 = blockIdx.y * TILE_S;
    const int p  = blockIdx.x * THREADS + threadIdx.x;   // pixel index in [0, HW)

    // ---- per-(b,s) softmax over K=21, rows s0..s0+31, padded to 24 with zeros ----
    if (threadIdx.x < TILE_S) {
        const int s = s0 + threadIdx.x;
        const float* m = ada_mask + ((size_t)b * S_DIM + s) * K_DIM;
        float mv[K_DIM];
        float mx = -3.402823466e+38f;
        #pragma unroll
        for (int k = 0; k < K_DIM; ++k) { mv[k] = m[k]; mx = fmaxf(mx, mv[k]); }
        float sum = 0.f;
        #pragma unroll
        for (int k = 0; k < K_DIM; ++k) { mv[k] = expf(mv[k] - mx); sum += mv[k]; }
        const float inv = 1.0f / sum;
        #pragma unroll
        for (int k = 0; k < K_DIM; ++k) ws[threadIdx.x * WROW + k] = mv[k] * inv;
        ws[threadIdx.x * WROW + 21] = 0.f;
        ws[threadIdx.x * WROW + 22] = 0.f;
        ws[threadIdx.x * WROW + 23] = 0.f;
    }
    __syncthreads();

    // ---- load 55-plane input window for this s-tile into registers ----
    // window covers s in [s0-PAD, s0-PAD+WIN-1]; out-of-range -> 0 (zero padding).
    // Clipped entries are exactly 0.0f, so zero weights * them stay finite.
    float win[WIN];
    const float* xb = x + (size_t)b * S_DIM * HW_DIM + p;
    #pragma unroll
    for (int i = 0; i < WIN; ++i) {
        const int s = s0 - PAD + i;
        win[i] = (s >= 0 && s < S_DIM) ? xb[(size_t)s * HW_DIM] : 0.f;
    }

    // ---- 32 outputs: each is a 24-wide dot (last 3 weights are zero) ----
    float* ob = out + ((size_t)b * S_DIM + s0) * HW_DIM + p;
    #pragma unroll
    for (int j = 0; j < TILE_S; ++j) {
        const float4* wr = reinterpret_cast<const float4*>(ws + j * WROW);
        // 4 partial accumulators to break the FMA dependency chain
        float a0 = 0.f, a1 = 0.f, a2 = 0.f, a3 = 0.f;
        #pragma unroll
        for (int q = 0; q < 6; ++q) {
            const float4 w4 = wr[q];
            a0 = fmaf(w4.x, win[j + 4*q + 0], a0);
            a1 = fmaf(w4.y, win[j + 4*q + 1], a1);
            a2 = fmaf(w4.z, win[j + 4*q + 2], a2);
            a3 = fmaf(w4.w, win[j + 4*q + 3], a3);
        }
        ob[(size_t)j * HW_DIM] = (a0 + a1) + (a2 + a3);
    }
}

extern "C" void kernel_launch(void* const* d_in, const int* in_sizes, int n_in,
                              void* d_out, int out_size)
{
    const float* x        = (const float*)d_in[0];   // (4,128,128,128) fp32
    const float* ada_mask = (const float*)d_in[1];   // (4,128,21) fp32
    float* out            = (float*)d_out;

    dim3 grid(HW_DIM / THREADS,   // 64 pixel-blocks
              S_DIM / TILE_S,     // 4 s-tiles
              B_DIM);             // 4 batches
    AdaptiveMixing_28784870818046_kernel<<<grid, THREADS>>>(x, ada_mask, out);
}

// round 3
// speedup vs baseline: 1.2509x; 1.2509x over previous
#include <cuda_runtime.h>
#include <math.h>

// x: (B=4, S=128, H=128, W=128) fp32 ; ada_mask: (B, S, K=21) fp32
// out[b,s,h,w] = sum_k softmax(ada_mask[b,s,:])[k] * xpad[b, s+k-10, h, w]
#define B_DIM    4
#define S_DIM    128
#define HW_DIM   16384                 // H*W  (pixels)
#define HW2_DIM  8192                  // H*W / 2 (float2 pixels)
#define K_DIM    21
#define PAD      10
#define TILE_S   32                    // output rows (s) per thread
#define THREADS  128
#define WROW     24                    // weight row padded to 24 (zeros at 21..23)
#define WIN      (TILE_S + WROW - 1)   // 55 input planes per tile

__global__ __launch_bounds__(THREADS, 4)
void AdaptiveMixing_28784870818046_kernel(const float2* __restrict__ x,
                                          const float*  __restrict__ ada_mask,
                                          float2* __restrict__ out)
{
    __shared__ __align__(16) float ws[TILE_S * WROW];

    const int b  = blockIdx.z;
    const int s0 = blockIdx.y * TILE_S;
    const int p  = blockIdx.x * THREADS + threadIdx.x;   // float2-pixel index in [0, HW2)

    // ---- per-(b,s) softmax over K=21 for rows s0..s0+31, padded to 24 with zeros ----
    if (threadIdx.x < TILE_S) {
        const int s = s0 + threadIdx.x;
        const float* m = ada_mask + ((size_t)b * S_DIM + s) * K_DIM;
        float mv[K_DIM];
        float mx = -3.402823466e+38f;
        #pragma unroll
        for (int k = 0; k < K_DIM; ++k) { mv[k] = m[k]; mx = fmaxf(mx, mv[k]); }
        float sum = 0.f;
        #pragma unroll
        for (int k = 0; k < K_DIM; ++k) { mv[k] = expf(mv[k] - mx); sum += mv[k]; }
        const float inv = 1.0f / sum;
        #pragma unroll
        for (int k = 0; k < K_DIM; ++k) ws[threadIdx.x * WROW + k] = mv[k] * inv;
        ws[threadIdx.x * WROW + 21] = 0.f;
        ws[threadIdx.x * WROW + 22] = 0.f;
        ws[threadIdx.x * WROW + 23] = 0.f;
    }
    __syncthreads();

    // ---- load the 55-plane float2 window for this s-tile into registers ----
    // Out-of-range s -> (0,0): matches zero padding; zero weights keep it exact.
    float2 win[WIN];
    const float2* xb = x + (size_t)b * S_DIM * HW2_DIM + p;
    #pragma unroll
    for (int i = 0; i < WIN; ++i) {
        const int s = s0 - PAD + i;
        if (s >= 0 && s < S_DIM) {
            win[i] = xb[(size_t)s * HW2_DIM];
        } else {
            win[i] = make_float2(0.f, 0.f);
        }
    }

    // ---- 32 output rows: each a 24-wide dot on a float2 pixel pair ----
    float2* ob = out + ((size_t)b * S_DIM + s0) * HW2_DIM + p;
    #pragma unroll
    for (int j = 0; j < TILE_S; ++j) {
        const float4* wr = reinterpret_cast<const float4*>(ws + j * WROW);
        float a0x = 0.f, a0y = 0.f, a1x = 0.f, a1y = 0.f;
        #pragma unroll
        for (int q = 0; q < 6; ++q) {
            const float4 w4 = wr[q];
            const float2 v0 = win[j + 4*q + 0];
            const float2 v1 = win[j + 4*q + 1];
            const float2 v2 = win[j + 4*q + 2];
            const float2 v3 = win[j + 4*q + 3];
            a0x = fmaf(w4.x, v0.x, a0x);  a0y = fmaf(w4.x, v0.y, a0y);
            a1x = fmaf(w4.y, v1.x, a1x);  a1y = fmaf(w4.y, v1.y, a1y);
            a0x = fmaf(w4.z, v2.x, a0x);  a0y = fmaf(w4.z, v2.y, a0y);
            a1x = fmaf(w4.w, v3.x, a1x);  a1y = fmaf(w4.w, v3.y, a1y);
        }
        float2 r;
        r.x = a0x + a1x;
        r.y = a0y + a1y;
        ob[(size_t)j * HW2_DIM] = r;
    }
}

extern "C" void kernel_launch(void* const* d_in, const int* in_sizes, int n_in,
                              void* d_out, int out_size)
{
    const float2* x       = (const float2*)d_in[0];   // (4,128,128,128) fp32 as float2
    const float* ada_mask = (const float*)d_in[1];    // (4,128,21) fp32
    float2* out           = (float2*)d_out;

    dim3 grid(HW2_DIM / THREADS,   // 64 pixel-blocks
              S_DIM / TILE_S,      // 4 s-tiles
              B_DIM);              // 4 batches
    AdaptiveMixing_28784870818046_kernel<<<grid, THREADS>>>(x, ada_mask, out);
}